// round 1
// baseline (speedup 1.0000x reference)
#include <cuda_runtime.h>
#include <math.h>

#define N_NODES 4096
#define NFEAT   128
#define NHID    128
#define NHEADS  4
#define NCLASS  32
#define KEDGE   32
#define ALPHA_LRELU 0.2f

// ---------------- scratch (no allocations allowed) ----------------
__device__ float g_h  [N_NODES * NHEADS * NHID];   // [n][head*128+d]
__device__ float g_xc [N_NODES * NHEADS * NHID];   // [n][head*128+d]
__device__ float g_f1 [NHEADS * N_NODES];
__device__ float g_f2 [NHEADS * N_NODES];
__device__ float g_h2 [N_NODES * NCLASS];
__device__ float g_f1o[N_NODES];
__device__ float g_f2o[N_NODES];
__device__ int   g_cnt[N_NODES];
__device__ int   g_nbr[N_NODES * KEDGE];

// ---------------- K1: dedup neighbor lists ----------------
__global__ void k_nbrs(const int* __restrict__ edge) {
    int row  = blockIdx.x * 4 + (threadIdx.x >> 5);
    int lane = threadIdx.x & 31;
    int e = edge[row * KEDGE + lane];
    bool valid = (e >= 0);
    unsigned key = valid ? (unsigned)e : (0x40000000u + (unsigned)lane);
    unsigned grp = __match_any_sync(0xffffffffu, key);
    bool uniq = valid && ((__ffs(grp) - 1) == lane);
    unsigned bal = __ballot_sync(0xffffffffu, uniq);
    if (uniq) {
        int pos = __popc(bal & ((1u << lane) - 1u));
        g_nbr[row * KEDGE + pos] = e;   // local index within 1024-block
    }
    if (lane == 0) g_cnt[row] = __popc(bal);
}

// ---------------- K2: h = x @ concat(Ws) ----------------
// C[4096 x 512], A = x [4096 x 128], B per head = Ws[h] [128 x 128]
__global__ void k_gemm1(const float* __restrict__ X, const float* __restrict__ Ws) {
    __shared__ float As[64][65];  // [k][m]
    __shared__ float Bs[64][65];  // [k][n]
    int bx = blockIdx.x;          // 0..7  (64-col tiles of 512)
    int by = blockIdx.y;          // 0..63 (64-row tiles of 4096)
    int n0 = bx * 64;
    int head = n0 >> 7;
    int nloc = n0 & 127;
    const float* B = Ws + head * NFEAT * NHID;
    int m0 = by * 64;
    int tid = threadIdx.x;
    int tx = tid & 15, ty = tid >> 4;

    float acc[4][4] = {};
    for (int kc = 0; kc < NFEAT; kc += 64) {
        #pragma unroll
        for (int t = 0; t < 16; t++) {
            int e = t * 256 + tid;
            { int k = e & 63, m = e >> 6;      // A: coalesced over k
              As[k][m] = X[(m0 + m) * NFEAT + kc + k]; }
            { int n = e & 63, k = e >> 6;      // B: coalesced over n
              Bs[k][n] = B[(kc + k) * NHID + nloc + n]; }
        }
        __syncthreads();
        #pragma unroll 16
        for (int kk = 0; kk < 64; kk++) {
            float av[4], bv[4];
            #pragma unroll
            for (int i = 0; i < 4; i++) av[i] = As[kk][ty * 4 + i];
            #pragma unroll
            for (int j = 0; j < 4; j++) bv[j] = Bs[kk][tx * 4 + j];
            #pragma unroll
            for (int i = 0; i < 4; i++)
                #pragma unroll
                for (int j = 0; j < 4; j++)
                    acc[i][j] += av[i] * bv[j];
        }
        __syncthreads();
    }
    #pragma unroll
    for (int i = 0; i < 4; i++) {
        float4 v = make_float4(acc[i][0], acc[i][1], acc[i][2], acc[i][3]);
        *(float4*)&g_h[(m0 + ty * 4 + i) * 512 + n0 + tx * 4] = v;
    }
}

// ---------------- K3: f1/f2 per (row, head) ----------------
__global__ void k_f12(const float* __restrict__ a) {
    int w    = blockIdx.x * 4 + (threadIdx.x >> 5);
    int row  = w >> 2;
    int head = w & 3;
    int lane = threadIdx.x & 31;
    const float* hp = g_h + row * 512 + head * 128;
    const float* ap = a + head * 256;
    float s1 = 0.f, s2 = 0.f;
    #pragma unroll
    for (int c = 0; c < 4; c++) {
        float hv = hp[lane + 32 * c];
        s1 += hv * ap[lane + 32 * c];
        s2 += hv * ap[128 + lane + 32 * c];
    }
    #pragma unroll
    for (int o = 16; o; o >>= 1) {
        s1 += __shfl_xor_sync(0xffffffffu, s1, o);
        s2 += __shfl_xor_sync(0xffffffffu, s2, o);
    }
    if (lane == 0) {
        g_f1[head * N_NODES + row] = s1;
        g_f2[head * N_NODES + row] = s2;
    }
}

// ---------------- K4: layer-1 sparse attention + elu ----------------
__global__ void k_attn1() {
    int row  = blockIdx.x;
    int head = threadIdx.x >> 5;
    int lane = threadIdx.x & 31;
    int base = row & ~1023;
    int cnt  = g_cnt[row];

    int j = 0;
    float e = -INFINITY;
    if (lane < cnt) {
        j = g_nbr[row * KEDGE + lane];
        float t = g_f1[head * N_NODES + row] + g_f2[head * N_NODES + base + j];
        e = (t > 0.f) ? t : ALPHA_LRELU * t;
    }
    float m = e;
    #pragma unroll
    for (int o = 16; o; o >>= 1) m = fmaxf(m, __shfl_xor_sync(0xffffffffu, m, o));
    float p = (lane < cnt) ? __expf(e - m) : 0.f;
    float s = p;
    #pragma unroll
    for (int o = 16; o; o >>= 1) s += __shfl_xor_sync(0xffffffffu, s, o);
    float wgt = p / s;

    float4 acc = make_float4(0.f, 0.f, 0.f, 0.f);
    for (int k = 0; k < cnt; k++) {
        float wk = __shfl_sync(0xffffffffu, wgt, k);
        int   jk = __shfl_sync(0xffffffffu, j, k);
        float4 hv = *(const float4*)&g_h[(base + jk) * 512 + head * 128 + lane * 4];
        acc.x += wk * hv.x; acc.y += wk * hv.y;
        acc.z += wk * hv.z; acc.w += wk * hv.w;
    }
    float4 o4;
    o4.x = acc.x > 0.f ? acc.x : expm1f(acc.x);
    o4.y = acc.y > 0.f ? acc.y : expm1f(acc.y);
    o4.z = acc.z > 0.f ? acc.z : expm1f(acc.z);
    o4.w = acc.w > 0.f ? acc.w : expm1f(acc.w);
    *(float4*)&g_xc[row * 512 + head * 128 + lane * 4] = o4;
}

// ---------------- K5: h2 = xc @ W_out, fused f1o/f2o ----------------
__global__ void k_gemm2(const float* __restrict__ W, const float* __restrict__ a_out) {
    __shared__ float Xs[32][132];   // [row][k] natural layout (warp-uniform reads)
    __shared__ float Wsm[128][33];  // [k][n]
    int r0 = blockIdx.x * 32;
    int tid = threadIdx.x;
    int lane = tid & 31, wid = tid >> 5;  // warp -> 4 rows

    float acc[4] = {0.f, 0.f, 0.f, 0.f};
    for (int kc = 0; kc < 512; kc += 128) {
        #pragma unroll
        for (int t = 0; t < 16; t++) {
            int e = t * 256 + tid;
            { int r = e >> 7, k = e & 127;
              Xs[r][k] = g_xc[(r0 + r) * 512 + kc + k]; }
            { int k = e >> 5, n = e & 31;
              Wsm[k][n] = W[(kc + k) * 32 + n]; }
        }
        __syncthreads();
        #pragma unroll 8
        for (int kk = 0; kk < 128; kk++) {
            float w = Wsm[kk][lane];
            #pragma unroll
            for (int r = 0; r < 4; r++) acc[r] += Xs[wid * 4 + r][kk] * w;
        }
        __syncthreads();
    }
    float a1 = a_out[lane];
    float a2 = a_out[32 + lane];
    #pragma unroll
    for (int r = 0; r < 4; r++) {
        int row = r0 + wid * 4 + r;
        g_h2[row * 32 + lane] = acc[r];
        float s1 = acc[r] * a1;
        float s2 = acc[r] * a2;
        #pragma unroll
        for (int o = 16; o; o >>= 1) {
            s1 += __shfl_xor_sync(0xffffffffu, s1, o);
            s2 += __shfl_xor_sync(0xffffffffu, s2, o);
        }
        if (lane == 0) { g_f1o[row] = s1; g_f2o[row] = s2; }
    }
}

// ---------------- K6: layer-2 attention + elu + log_softmax ----------------
__global__ void k_attn2(float* __restrict__ out) {
    int row  = blockIdx.x * 4 + (threadIdx.x >> 5);
    int lane = threadIdx.x & 31;
    int base = row & ~1023;
    int cnt  = g_cnt[row];

    int j = 0;
    float e = -INFINITY;
    if (lane < cnt) {
        j = g_nbr[row * KEDGE + lane];
        float t = g_f1o[row] + g_f2o[base + j];
        e = (t > 0.f) ? t : ALPHA_LRELU * t;
    }
    float m = e;
    #pragma unroll
    for (int o = 16; o; o >>= 1) m = fmaxf(m, __shfl_xor_sync(0xffffffffu, m, o));
    float p = (lane < cnt) ? __expf(e - m) : 0.f;
    float s = p;
    #pragma unroll
    for (int o = 16; o; o >>= 1) s += __shfl_xor_sync(0xffffffffu, s, o);
    float wgt = p / s;

    float acc = 0.f;
    for (int k = 0; k < cnt; k++) {
        float wk = __shfl_sync(0xffffffffu, wgt, k);
        int   jk = __shfl_sync(0xffffffffu, j, k);
        acc += wk * g_h2[(base + jk) * 32 + lane];
    }
    float v = acc > 0.f ? acc : expm1f(acc);
    // log_softmax over the 32 lanes
    float m2 = v;
    #pragma unroll
    for (int o = 16; o; o >>= 1) m2 = fmaxf(m2, __shfl_xor_sync(0xffffffffu, m2, o));
    float se = __expf(v - m2);
    #pragma unroll
    for (int o = 16; o; o >>= 1) se += __shfl_xor_sync(0xffffffffu, se, o);
    out[row * 32 + lane] = v - m2 - logf(se);
}

// ---------------- launch ----------------
extern "C" void kernel_launch(void* const* d_in, const int* in_sizes, int n_in,
                              void* d_out, int out_size) {
    const float* x     = (const float*)d_in[0];
    const int*   edge  = (const int*)d_in[1];
    // d_in[2] = node_num (1024, fixed)
    const float* Ws    = (const float*)d_in[3];
    const float* a     = (const float*)d_in[4];
    const float* W_out = (const float*)d_in[5];
    const float* a_out = (const float*)d_in[6];
    float* out = (float*)d_out;

    k_nbrs<<<N_NODES / 4, 128>>>(edge);
    dim3 g1(8, 64);
    k_gemm1<<<g1, 256>>>(x, Ws);
    k_f12<<<N_NODES, 128>>>(a);
    k_attn1<<<N_NODES, 128>>>();
    k_gemm2<<<N_NODES / 32, 256>>>(W_out, a_out);
    k_attn2<<<N_NODES / 4, 128>>>(out);
}